// round 1
// baseline (speedup 1.0000x reference)
#include <cuda_runtime.h>
#include <cuda_bf16.h>
#include <cstdint>

// PQLinear: out[M=8192, N=4096] = X[M, K=4096] @ W^T
// W[o, k] = codebooks[s, assignments[o, s], k % 128],  s = k / 128
//
// Round 1: fp32 register-tiled SGEMM (128x128x32 tile, 8x8 per-thread) with
// the PQ gather fused into the B-tile shared-memory load. Codebooks (4 MB)
// stay L2-resident, so the gather is cheap relative to the FMA-bound mainloop.

#define IN_F   4096
#define OUT_F  4096
#define NSUB   32
#define NCENT  256
#define DSUB   128

#define BM 128
#define BN 128
#define BK 32

__global__ __launch_bounds__(256, 2) void pq_gemm_kernel(
    const float* __restrict__ x,          // [M, IN_F]
    const float* __restrict__ codebooks,  // [NSUB, NCENT, DSUB]
    const int*   __restrict__ assign,     // [OUT_F, NSUB]
    float*       __restrict__ out)        // [M, OUT_F]
{
    __shared__ float As[BK][BM];   // transposed A tile
    __shared__ float Bs[BK][BN];   // gathered W tile (k-major)

    const int tid = threadIdx.x;
    const int tx  = tid & 15;      // 0..15  -> N quadrant offset
    const int ty  = tid >> 4;      // 0..15  -> M quadrant offset
    const int n0  = blockIdx.x * BN;
    const int m0  = blockIdx.y * BM;

    float acc[8][8];
#pragma unroll
    for (int i = 0; i < 8; i++)
#pragma unroll
        for (int j = 0; j < 8; j++) acc[i][j] = 0.f;

    // A-load mapping: 256 threads, each pass covers 32 rows x 8 float4 (32 cols)
    const int a_row  = tid >> 3;   // 0..31
    const int a_col4 = tid & 7;    // 0..7
    // B-gather mapping: each thread owns one output column half-chunk
    const int b_o    = tid >> 1;   // 0..127  (column within tile)
    const int b_half = tid & 1;    // 0..1    (16-element half of the 32-wide k chunk)

    for (int k0 = 0; k0 < IN_F; k0 += BK) {
        // ---- load A tile, transposed into As[k][m] ----
#pragma unroll
        for (int p = 0; p < 4; p++) {
            const int row = a_row + p * 32;
            const float4 v = *reinterpret_cast<const float4*>(
                &x[(size_t)(m0 + row) * IN_F + k0 + a_col4 * 4]);
            const int kk = a_col4 * 4;
            As[kk + 0][row] = v.x;
            As[kk + 1][row] = v.y;
            As[kk + 2][row] = v.z;
            As[kk + 3][row] = v.w;
        }

        // ---- gather B tile from codebooks (L2-resident) ----
        {
            const int s    = k0 >> 7;                       // subvector index
            const int off0 = (k0 & 127) + b_half * 16;      // offset within subvector
            const int code = assign[(size_t)(n0 + b_o) * NSUB + s];
            const float* src =
                codebooks + ((size_t)(s * NCENT + code) * DSUB) + off0;
#pragma unroll
            for (int q = 0; q < 4; q++) {
                const float4 v = *reinterpret_cast<const float4*>(src + q * 4);
                const int kk = b_half * 16 + q * 4;
                Bs[kk + 0][b_o] = v.x;
                Bs[kk + 1][b_o] = v.y;
                Bs[kk + 2][b_o] = v.z;
                Bs[kk + 3][b_o] = v.w;
            }
        }
        __syncthreads();

        // ---- FMA mainloop ----
#pragma unroll
        for (int k = 0; k < BK; k++) {
            float a[8], b[8];
            *reinterpret_cast<float4*>(&a[0]) =
                *reinterpret_cast<const float4*>(&As[k][ty * 4]);
            *reinterpret_cast<float4*>(&a[4]) =
                *reinterpret_cast<const float4*>(&As[k][64 + ty * 4]);
            *reinterpret_cast<float4*>(&b[0]) =
                *reinterpret_cast<const float4*>(&Bs[k][tx * 4]);
            *reinterpret_cast<float4*>(&b[4]) =
                *reinterpret_cast<const float4*>(&Bs[k][64 + tx * 4]);
#pragma unroll
            for (int i = 0; i < 8; i++)
#pragma unroll
                for (int j = 0; j < 8; j++)
                    acc[i][j] = fmaf(a[i], b[j], acc[i][j]);
        }
        __syncthreads();
    }

    // ---- epilogue: each thread writes 8 rows x 2 float4 ----
#pragma unroll
    for (int i = 0; i < 8; i++) {
        const int rloc = (i < 4) ? (ty * 4 + i) : (64 + ty * 4 + (i - 4));
        const size_t row = (size_t)(m0 + rloc);
#pragma unroll
        for (int jh = 0; jh < 2; jh++) {
            const int col = n0 + jh * 64 + tx * 4;
            float4 v = make_float4(acc[i][jh * 4 + 0], acc[i][jh * 4 + 1],
                                   acc[i][jh * 4 + 2], acc[i][jh * 4 + 3]);
            *reinterpret_cast<float4*>(&out[row * OUT_F + col]) = v;
        }
    }
}

extern "C" void kernel_launch(void* const* d_in, const int* in_sizes, int n_in,
                              void* d_out, int out_size) {
    const float* x         = (const float*)d_in[0];   // [4, 2048, 4096] fp32
    const float* codebooks = (const float*)d_in[1];   // [32, 256, 128] fp32
    const int*   assign    = (const int*)d_in[2];     // [4096, 32] int32
    float*       out       = (float*)d_out;           // [4, 2048, 4096] fp32

    dim3 grid(OUT_F / BN, (4 * 2048) / BM);           // (32, 64)
    pq_gemm_kernel<<<grid, 256>>>(x, codebooks, assign, out);
}

// round 4
// speedup vs baseline: 3.4953x; 3.4953x over previous
#include <cuda_runtime.h>
#include <cuda_bf16.h>
#include <cstdint>

// PQLinear: out[8192,4096] = X[8192,4096] @ W^T, W gathered from PQ codebooks.
// R4: tf32 mma.sync.m16n8k8 warp-tiled GEMM (CTA 128x128x32, warp 32x64,
// 3-stage cp.async). FIX vs R3: g_Wr must be referenced from DEVICE code —
// passing the __device__ symbol from host passes the host shadow address,
// which GB300's ATS silently reads as zeros (rel_err was exactly 1.0).

#define M_TOT 8192
#define N_TOT 4096
#define K_TOT 4096
#define BM 128
#define BN 128
#define BK 32
#define SBK 36          // padded smem stride (floats): bank-conflict-free frag loads
#define STAGES 3
#define NCHUNK (K_TOT / BK)   // 128

__device__ float g_Wr[(size_t)N_TOT * K_TOT];   // 64 MB gathered W [N, K] row-major

// ---------------- helpers ----------------
__device__ __forceinline__ uint32_t smem_u32(const void* p) {
    uint32_t a;
    asm("{ .reg .u64 t; cvta.to.shared.u64 t, %1; cvt.u32.u64 %0, t; }" : "=r"(a) : "l"(p));
    return a;
}
__device__ __forceinline__ uint32_t rna_tf32(float f) {
    uint32_t o; asm("cvt.rna.tf32.f32 %0, %1;" : "=r"(o) : "f"(f)); return o;
}
__device__ __forceinline__ void cpa16(uint32_t saddr, const void* gaddr) {
    asm volatile("cp.async.cg.shared.global [%0], [%1], 16;" :: "r"(saddr), "l"(gaddr));
}
__device__ __forceinline__ void cp_commit() { asm volatile("cp.async.commit_group;" ::: "memory"); }
template <int N>
__device__ __forceinline__ void cp_wait() { asm volatile("cp.async.wait_group %0;" :: "n"(N) : "memory"); }

__device__ __forceinline__ void mma_tf32(float* c, const uint32_t* a, const uint32_t* b) {
    asm volatile(
        "mma.sync.aligned.m16n8k8.row.col.f32.tf32.tf32.f32 "
        "{%0,%1,%2,%3}, {%4,%5,%6,%7}, {%8,%9}, {%0,%1,%2,%3};"
        : "+f"(c[0]), "+f"(c[1]), "+f"(c[2]), "+f"(c[3])
        : "r"(a[0]), "r"(a[1]), "r"(a[2]), "r"(a[3]), "r"(b[0]), "r"(b[1]));
}

// ---------------- prep: gather W rows from codebooks ----------------
__global__ void build_w_kernel(const float* __restrict__ cb, const int* __restrict__ assign) {
    const int o = blockIdx.x;     // 0..4095
    const int j = threadIdx.x;    // 0..127
    float* wrow = &g_Wr[(size_t)o * K_TOT];
#pragma unroll 1
    for (int s = 0; s < 32; s++) {
        const int code = __ldg(&assign[o * 32 + s]);
        wrow[s * 128 + j] = cb[((size_t)(s * 256 + code)) * 128 + j];
    }
}

// ---------------- GEMM ----------------
#define STAGE_FLOATS (BM * SBK)                 // 4608 floats (A == B size)
#define SM_B_OFF (STAGES * STAGE_FLOATS)
#define SMEM_BYTES (2 * STAGES * STAGE_FLOATS * 4)

__global__ __launch_bounds__(256, 2) void pq_tf32_gemm(
    const float* __restrict__ A,   // X [M, K]
    float* __restrict__ out)
{
    const float* __restrict__ B = g_Wr;   // device-side symbol reference (correct addr)

    extern __shared__ float smem[];
    float* As = smem;              // [STAGES][BM][SBK]
    float* Bs = smem + SM_B_OFF;   // [STAGES][BN][SBK]
    const uint32_t sbase = smem_u32(smem);

    const int tid  = threadIdx.x;
    const int wid  = tid >> 5;
    const int lane = tid & 31;
    const int lq   = lane >> 2;    // 0..7
    const int lr   = lane & 3;     // 0..3

    // grid swizzle: 8x8 tile groups (A-rows + B-cols stay L2-resident)
    const int bid = blockIdx.x;
    const int grp = bid >> 6;
    const int r   = bid & 63;
    const int mt  = (grp & 7) * 8 + (r & 7);
    const int nt  = (grp >> 3) * 8 + (r >> 3);
    const int m0  = mt * BM;
    const int n0  = nt * BN;

    // warp tile: 4 warps down M (32 rows), 2 across N (64 cols)
    const int wm = (wid & 3) * 32;
    const int wn = (wid >> 2) * 64;

    float acc[2][8][4];
#pragma unroll
    for (int mi = 0; mi < 2; mi++)
#pragma unroll
        for (int ni = 0; ni < 8; ni++)
#pragma unroll
            for (int q = 0; q < 4; q++) acc[mi][ni][q] = 0.f;

    const int l_row = tid >> 3;    // 0..31
    const int l_c   = tid & 7;     // float4 column

    auto load_stage = [&](int chunk) {
        const int st = chunk % STAGES;
        const int k0 = chunk * BK;
        const uint32_t abase = sbase + (st * STAGE_FLOATS) * 4;
        const uint32_t bbase = sbase + ((SM_B_OFF + st * STAGE_FLOATS)) * 4;
#pragma unroll
        for (int p = 0; p < 4; p++) {
            const int row = l_row + p * 32;
            cpa16(abase + (row * SBK + l_c * 4) * 4,
                  A + (size_t)(m0 + row) * K_TOT + k0 + l_c * 4);
            cpa16(bbase + (row * SBK + l_c * 4) * 4,
                  B + (size_t)(n0 + row) * K_TOT + k0 + l_c * 4);
        }
    };

#pragma unroll
    for (int c = 0; c < STAGES - 1; c++) { load_stage(c); cp_commit(); }

#pragma unroll 1
    for (int i = 0; i < NCHUNK; i++) {
        if (i + STAGES - 1 < NCHUNK) load_stage(i + STAGES - 1);
        cp_commit();
        cp_wait<STAGES - 2>();
        __syncthreads();

        const float* as = As + (i % STAGES) * STAGE_FLOATS;
        const float* bs = Bs + (i % STAGES) * STAGE_FLOATS;

#pragma unroll
        for (int kk = 0; kk < BK; kk += 8) {
            uint32_t af[2][4], bf[8][2];
#pragma unroll
            for (int mi = 0; mi < 2; mi++) {
                const int row = wm + mi * 16 + lq;
                const float* p0 = as + row * SBK + kk + lr;
                af[mi][0] = rna_tf32(p0[0]);
                af[mi][1] = rna_tf32(p0[8 * SBK]);
                af[mi][2] = rna_tf32(p0[4]);
                af[mi][3] = rna_tf32(p0[8 * SBK + 4]);
            }
#pragma unroll
            for (int ni = 0; ni < 8; ni++) {
                const int col = wn + ni * 8 + lq;
                const float* p0 = bs + col * SBK + kk + lr;
                bf[ni][0] = rna_tf32(p0[0]);
                bf[ni][1] = rna_tf32(p0[4]);
            }
#pragma unroll
            for (int mi = 0; mi < 2; mi++)
#pragma unroll
                for (int ni = 0; ni < 8; ni++)
                    mma_tf32(acc[mi][ni], af[mi], bf[ni]);
        }
        __syncthreads();
    }

    // epilogue
#pragma unroll
    for (int mi = 0; mi < 2; mi++) {
#pragma unroll
        for (int ni = 0; ni < 8; ni++) {
            const int row0 = m0 + wm + mi * 16 + lq;
            const int col  = n0 + wn + ni * 8 + 2 * lr;
            float2* d0 = (float2*)&out[(size_t)row0 * N_TOT + col];
            float2* d1 = (float2*)&out[(size_t)(row0 + 8) * N_TOT + col];
            *d0 = make_float2(acc[mi][ni][0], acc[mi][ni][1]);
            *d1 = make_float2(acc[mi][ni][2], acc[mi][ni][3]);
        }
    }
}

extern "C" void kernel_launch(void* const* d_in, const int* in_sizes, int n_in,
                              void* d_out, int out_size) {
    const float* x         = (const float*)d_in[0];   // [4,2048,4096] fp32
    const float* codebooks = (const float*)d_in[1];   // [32,256,128] fp32
    const int*   assign    = (const int*)d_in[2];     // [4096,32] int32
    float*       out       = (float*)d_out;

    build_w_kernel<<<4096, 128>>>(codebooks, assign);

    cudaFuncSetAttribute(pq_tf32_gemm,
                         cudaFuncAttributeMaxDynamicSharedMemorySize, SMEM_BYTES);
    pq_tf32_gemm<<<(M_TOT / BM) * (N_TOT / BN), 256, SMEM_BYTES>>>(x, out);
}

// round 5
// speedup vs baseline: 4.3168x; 1.2350x over previous
#include <cuda_runtime.h>
#include <cuda_bf16.h>
#include <cstdint>

// PQLinear: out[8192,4096] = X[8192,4096] @ W^T (W gathered from PQ codebooks).
// R5: tf32 mma.sync GEMM, mainloop = pure LDS.64 + HMMA.
//  - tf32 RNA rounding hoisted into prep kernels (no cvts in mainloop)
//  - k-pair permuted global layout -> every fragment load is one ld.shared.v2.f32
//  - smem stride 40 floats -> conflict-free 64-bit LDS
//  - warp tile 64x64 (4 warps, CTA 128x128), 2-stage cp.async, 2 CTAs/SM

#define M_TOT 8192
#define N_TOT 4096
#define K_TOT 4096
#define BM 128
#define BN 128
#define BK 32
#define SBK 40
#define STAGES 2
#define NCHUNK (K_TOT / BK)          // 128
#define STAGE_FLOATS (BM * SBK)      // 5120
#define SM_B_OFF (STAGES * STAGE_FLOATS)
#define SMEM_BYTES (2 * STAGES * STAGE_FLOATS * 4)   // 81920

__device__ float g_Xr[(size_t)M_TOT * K_TOT];   // rounded + k-permuted X
__device__ float g_Wr[(size_t)N_TOT * K_TOT];   // gathered + rounded + k-permuted W

// ---------------- helpers ----------------
__device__ __forceinline__ uint32_t smem_u32(const void* p) {
    uint32_t a;
    asm("{ .reg .u64 t; cvta.to.shared.u64 t, %1; cvt.u32.u64 %0, t; }" : "=r"(a) : "l"(p));
    return a;
}
__device__ __forceinline__ float rna_tf32f(float f) {
    uint32_t o; asm("cvt.rna.tf32.f32 %0, %1;" : "=r"(o) : "f"(f));
    return __uint_as_float(o);
}
__device__ __forceinline__ void cpa16(uint32_t saddr, const void* gaddr) {
    asm volatile("cp.async.cg.shared.global [%0], [%1], 16;" :: "r"(saddr), "l"(gaddr));
}
__device__ __forceinline__ void cp_commit() { asm volatile("cp.async.commit_group;" ::: "memory"); }
template <int N>
__device__ __forceinline__ void cp_wait() { asm volatile("cp.async.wait_group %0;" :: "n"(N) : "memory"); }

__device__ __forceinline__ void mma_tf32(float* c, const uint32_t* a, const uint32_t* b) {
    asm volatile(
        "mma.sync.aligned.m16n8k8.row.col.f32.tf32.tf32.f32 "
        "{%0,%1,%2,%3}, {%4,%5,%6,%7}, {%8,%9}, {%0,%1,%2,%3};"
        : "+f"(c[0]), "+f"(c[1]), "+f"(c[2]), "+f"(c[3])
        : "r"(a[0]), "r"(a[1]), "r"(a[2]), "r"(a[3]), "r"(b[0]), "r"(b[1]));
}

// ---------------- prep: round X to tf32 + permute k pairs ----------------
// within each 8-k group, new layout = {k0,k4,k1,k5,k2,k6,k3,k7}
__global__ void prep_x_kernel(const float* __restrict__ x) {
    const size_t ngrp = (size_t)M_TOT * K_TOT / 8;
    for (size_t g = blockIdx.x * blockDim.x + threadIdx.x; g < ngrp;
         g += (size_t)gridDim.x * blockDim.x) {
        const float4* s = (const float4*)(x + g * 8);
        float4 a = s[0], b = s[1];             // k0..3, k4..7
        float4* d = (float4*)(g_Xr + g * 8);
        d[0] = make_float4(rna_tf32f(a.x), rna_tf32f(b.x), rna_tf32f(a.y), rna_tf32f(b.y));
        d[1] = make_float4(rna_tf32f(a.z), rna_tf32f(b.z), rna_tf32f(a.w), rna_tf32f(b.w));
    }
}

// gather W rows, round to tf32, permute k pairs
__global__ void build_w_kernel(const float* __restrict__ cb, const int* __restrict__ assign) {
    const int o = blockIdx.x;     // 0..4095
    const int j = threadIdx.x;    // 0..127 within subvector
    const int p  = j & 7;
    const int np = (p < 4) ? (2 * p) : (2 * p - 7);
    const int jd = (j & ~7) + np;
    float* wrow = &g_Wr[(size_t)o * K_TOT];
#pragma unroll 1
    for (int s = 0; s < 32; s++) {
        const int code = __ldg(&assign[o * 32 + s]);
        wrow[s * 128 + jd] = rna_tf32f(cb[((size_t)(s * 256 + code)) * 128 + j]);
    }
}

// ---------------- GEMM ----------------
__global__ __launch_bounds__(128, 2) void pq_tf32_gemm(
    float* __restrict__ out)
{
    const float* __restrict__ A = g_Xr;
    const float* __restrict__ B = g_Wr;

    extern __shared__ float smem[];
    float* As = smem;               // [STAGES][BM][SBK]
    float* Bs = smem + SM_B_OFF;    // [STAGES][BN][SBK]
    const uint32_t sbase = smem_u32(smem);

    const int tid  = threadIdx.x;
    const int wid  = tid >> 5;      // 0..3
    const int lane = tid & 31;
    const int lq   = lane >> 2;     // 0..7
    const int lr   = lane & 3;      // 0..3

    // grid swizzle: 8x8 tile groups (keeps 32MB working set L2-resident)
    const int bid = blockIdx.x;
    const int grp = bid >> 6;
    const int r   = bid & 63;
    const int mt  = (grp & 7) * 8 + (r & 7);
    const int nt  = (grp >> 3) * 8 + (r >> 3);
    const int m0  = mt * BM;
    const int n0  = nt * BN;

    // warp tile: 2x2 warps of 64x64
    const int wm = (wid >> 1) * 64;
    const int wn = (wid & 1) * 64;

    float acc[4][8][4];
#pragma unroll
    for (int mi = 0; mi < 4; mi++)
#pragma unroll
        for (int ni = 0; ni < 8; ni++)
#pragma unroll
            for (int q = 0; q < 4; q++) acc[mi][ni][q] = 0.f;

    // stage load: per operand 128 rows x 8 float4; 128 threads -> 8 f4 each
    const int l_row = tid >> 3;     // 0..15
    const int l_c   = tid & 7;

    auto load_stage = [&](int chunk) {
        const int st = chunk & (STAGES - 1);
        const int k0 = chunk * BK;
        const uint32_t abase = sbase + (st * STAGE_FLOATS) * 4;
        const uint32_t bbase = sbase + ((SM_B_OFF + st * STAGE_FLOATS)) * 4;
#pragma unroll
        for (int p = 0; p < 8; p++) {
            const int row = l_row + p * 16;
            cpa16(abase + (row * SBK + l_c * 4) * 4,
                  A + (size_t)(m0 + row) * K_TOT + k0 + l_c * 4);
            cpa16(bbase + (row * SBK + l_c * 4) * 4,
                  B + (size_t)(n0 + row) * K_TOT + k0 + l_c * 4);
        }
    };

    load_stage(0);
    cp_commit();

#pragma unroll 1
    for (int i = 0; i < NCHUNK; i++) {
        if (i + 1 < NCHUNK) load_stage(i + 1);
        cp_commit();
        cp_wait<1>();
        __syncthreads();

        const float* as = As + (i & (STAGES - 1)) * STAGE_FLOATS;
        const float* bs = Bs + (i & (STAGES - 1)) * STAGE_FLOATS;

#pragma unroll
        for (int kg = 0; kg < 4; kg++) {        // kk = kg*8
            const int kb = kg * 8 + 2 * lr;     // permuted pair offset
            uint32_t af[4][4], bf[8][2];
#pragma unroll
            for (int mi = 0; mi < 4; mi++) {
                const int rw = wm + mi * 16 + lq;
                const float2 v0 = *(const float2*)(as + rw * SBK + kb);
                const float2 v1 = *(const float2*)(as + (rw + 8) * SBK + kb);
                af[mi][0] = __float_as_uint(v0.x);
                af[mi][1] = __float_as_uint(v1.x);
                af[mi][2] = __float_as_uint(v0.y);
                af[mi][3] = __float_as_uint(v1.y);
            }
#pragma unroll
            for (int ni = 0; ni < 8; ni++) {
                const int cw = wn + ni * 8 + lq;
                const float2 v = *(const float2*)(bs + cw * SBK + kb);
                bf[ni][0] = __float_as_uint(v.x);
                bf[ni][1] = __float_as_uint(v.y);
            }
#pragma unroll
            for (int mi = 0; mi < 4; mi++)
#pragma unroll
                for (int ni = 0; ni < 8; ni++)
                    mma_tf32(acc[mi][ni], af[mi], bf[ni]);
        }
        __syncthreads();
    }

    // epilogue: float2 stores
#pragma unroll
    for (int mi = 0; mi < 4; mi++) {
#pragma unroll
        for (int ni = 0; ni < 8; ni++) {
            const int row0 = m0 + wm + mi * 16 + lq;
            const int col  = n0 + wn + ni * 8 + 2 * lr;
            *(float2*)&out[(size_t)row0 * N_TOT + col] =
                make_float2(acc[mi][ni][0], acc[mi][ni][1]);
            *(float2*)&out[(size_t)(row0 + 8) * N_TOT + col] =
                make_float2(acc[mi][ni][2], acc[mi][ni][3]);
        }
    }
}

extern "C" void kernel_launch(void* const* d_in, const int* in_sizes, int n_in,
                              void* d_out, int out_size) {
    const float* x         = (const float*)d_in[0];   // [4,2048,4096] fp32
    const float* codebooks = (const float*)d_in[1];   // [32,256,128] fp32
    const int*   assign    = (const int*)d_in[2];     // [4096,32] int32
    float*       out       = (float*)d_out;

    prep_x_kernel<<<8192, 256>>>(x);
    build_w_kernel<<<4096, 128>>>(codebooks, assign);

    cudaFuncSetAttribute(pq_tf32_gemm,
                         cudaFuncAttributeMaxDynamicSharedMemorySize, SMEM_BYTES);
    pq_tf32_gemm<<<(M_TOT / BM) * (N_TOT / BN), 128, SMEM_BYTES>>>(out);
}